// round 1
// baseline (speedup 1.0000x reference)
#include <cuda_runtime.h>
#include <math.h>

// Problem shape (fixed by the dataset): B=16384, D=1024, grid 32x32 -> N=1024
#define BM 128
#define BN 128
#define BK 8

// Scratch (allocation-free rule: __device__ globals)
__device__ float g_logits[16384ull * 1024];   // logits -> combined (in place)
__device__ float g_wsq[1024];

// ---------------------------------------------------------------------------
// ||w_n||^2 for each of the 1024 codebook vectors
// ---------------------------------------------------------------------------
__global__ void wsq_kernel(const float* __restrict__ W, float* __restrict__ wsq) {
    const int n   = blockIdx.x;
    const int tid = threadIdx.x;  // 256
    const float4 v = *reinterpret_cast<const float4*>(W + (size_t)n * 1024 + tid * 4);
    float s = v.x * v.x + v.y * v.y + v.z * v.z + v.w * v.w;
    __shared__ float red[256];
    red[tid] = s;
    __syncthreads();
    #pragma unroll
    for (int st = 128; st > 0; st >>= 1) {
        if (tid < st) red[tid] += red[tid + st];
        __syncthreads();
    }
    if (tid == 0) wsq[n] = red[0];
}

// ---------------------------------------------------------------------------
// 128x128x8 double-buffered SGEMM, 256 threads, 8x8 per thread.
// C[m,n] = sum_k A[m,k] * B[n,k]   (TRANSB=true,  B is [N,K] row-major)
// C[m,n] = sum_k A[m,k] * B[k,n]   (TRANSB=false, B is [K,N] row-major)
// EPI==1: C = 2*acc - wsq[n]  (fused logits epilogue)
// ---------------------------------------------------------------------------
template<int EPI, bool TRANSB>
__global__ __launch_bounds__(256, 2)
void sgemm_kernel(const float* __restrict__ A, const float* __restrict__ B,
                  float* __restrict__ C, int M, int N, int K,
                  const float* __restrict__ wsq)
{
    __shared__ float As[2][BK][BM];
    __shared__ float Bs[2][BK][BN];

    const int tid = threadIdx.x;
    const int bx  = blockIdx.x;   // n-tile
    const int by  = blockIdx.y;   // m-tile

    // A tile loader: 128 rows x 8 k, one float4 along k per thread
    const int a_row = tid >> 1;
    const int a_kc  = (tid & 1) * 4;
    const float* Ag = A + (size_t)(by * BM + a_row) * K + a_kc;

    // B tile loader
    const float* Bg;
    int b_row = 0, b_kc = 0, b_kr = 0, b_col = 0;
    if (TRANSB) {
        b_row = tid >> 1;
        b_kc  = (tid & 1) * 4;
        Bg = B + (size_t)(bx * BN + b_row) * K + b_kc;
    } else {
        b_kr  = tid >> 5;
        b_col = (tid & 31) * 4;
        Bg = B + (size_t)b_kr * N + bx * BN + b_col;
    }

    const int rm = tid >> 4;   // 0..15
    const int rn = tid & 15;   // 0..15

    float acc[8][8];
    #pragma unroll
    for (int i = 0; i < 8; i++)
        #pragma unroll
        for (int j = 0; j < 8; j++) acc[i][j] = 0.f;

    // Preload tile 0
    {
        float4 a = *reinterpret_cast<const float4*>(Ag);
        As[0][a_kc + 0][a_row] = a.x; As[0][a_kc + 1][a_row] = a.y;
        As[0][a_kc + 2][a_row] = a.z; As[0][a_kc + 3][a_row] = a.w;
        if (TRANSB) {
            float4 b = *reinterpret_cast<const float4*>(Bg);
            Bs[0][b_kc + 0][b_row] = b.x; Bs[0][b_kc + 1][b_row] = b.y;
            Bs[0][b_kc + 2][b_row] = b.z; Bs[0][b_kc + 3][b_row] = b.w;
        } else {
            *reinterpret_cast<float4*>(&Bs[0][b_kr][b_col]) =
                *reinterpret_cast<const float4*>(Bg);
        }
    }
    __syncthreads();

    int buf = 0;
    const int T = K / BK;
    for (int t = 0; t < T; t++) {
        float4 an, bn;
        const bool has_next = (t + 1 < T);
        if (has_next) {
            an = *reinterpret_cast<const float4*>(Ag + (t + 1) * BK);
            bn = TRANSB
               ? *reinterpret_cast<const float4*>(Bg + (t + 1) * BK)
               : *reinterpret_cast<const float4*>(Bg + (size_t)(t + 1) * BK * N);
        }
        #pragma unroll
        for (int kk = 0; kk < BK; kk++) {
            float ar[8], br[8];
            *reinterpret_cast<float4*>(&ar[0]) = *reinterpret_cast<const float4*>(&As[buf][kk][rm * 4]);
            *reinterpret_cast<float4*>(&ar[4]) = *reinterpret_cast<const float4*>(&As[buf][kk][rm * 4 + 64]);
            *reinterpret_cast<float4*>(&br[0]) = *reinterpret_cast<const float4*>(&Bs[buf][kk][rn * 4]);
            *reinterpret_cast<float4*>(&br[4]) = *reinterpret_cast<const float4*>(&Bs[buf][kk][rn * 4 + 64]);
            #pragma unroll
            for (int i = 0; i < 8; i++)
                #pragma unroll
                for (int j = 0; j < 8; j++)
                    acc[i][j] = fmaf(ar[i], br[j], acc[i][j]);
        }
        if (has_next) {
            buf ^= 1;
            As[buf][a_kc + 0][a_row] = an.x; As[buf][a_kc + 1][a_row] = an.y;
            As[buf][a_kc + 2][a_row] = an.z; As[buf][a_kc + 3][a_row] = an.w;
            if (TRANSB) {
                Bs[buf][b_kc + 0][b_row] = bn.x; Bs[buf][b_kc + 1][b_row] = bn.y;
                Bs[buf][b_kc + 2][b_row] = bn.z; Bs[buf][b_kc + 3][b_row] = bn.w;
            } else {
                *reinterpret_cast<float4*>(&Bs[buf][b_kr][b_col]) = bn;
            }
            __syncthreads();
        }
    }

    // Epilogue
    #pragma unroll
    for (int ii = 0; ii < 2; ii++) {
        #pragma unroll
        for (int i = 0; i < 4; i++) {
            const int r = by * BM + ii * 64 + rm * 4 + i;
            #pragma unroll
            for (int jj = 0; jj < 2; jj++) {
                const int c0 = bx * BN + jj * 64 + rn * 4;
                const float* ap = &acc[ii * 4 + i][jj * 4];
                float4 o;
                if (EPI == 1) {
                    o.x = 2.f * ap[0] - __ldg(&wsq[c0 + 0]);
                    o.y = 2.f * ap[1] - __ldg(&wsq[c0 + 1]);
                    o.z = 2.f * ap[2] - __ldg(&wsq[c0 + 2]);
                    o.w = 2.f * ap[3] - __ldg(&wsq[c0 + 3]);
                } else {
                    o.x = ap[0]; o.y = ap[1]; o.z = ap[2]; o.w = ap[3];
                }
                *reinterpret_cast<float4*>(C + (size_t)r * N + c0) = o;
            }
        }
    }
}

// ---------------------------------------------------------------------------
// Per-row 32x32 double softmax + product + normalize (in place on logits).
// One block (256 threads) per batch row; n = g1*32 + g2.
//   e = exp(l - Mglobal); s1 = e/CS[g2]; s2 = e/RS[g1];
//   c = e^2/(RS*CS); out = c / (sum(c) + 1e-8)
// (softmax is shift-invariant, so the missing x_sq term and the global-max
//  shift are exact w.r.t. the reference)
// ---------------------------------------------------------------------------
__global__ void combine_kernel(float* __restrict__ L) {
    const int b   = blockIdx.x;
    const int tid = threadIdx.x;     // 256
    float* row = L + (size_t)b * 1024;

    __shared__ float sh_e[1024 + 32];  // stride-33 padded: idx = n + (n>>5)
    __shared__ float red[256];
    __shared__ float RS[32], CS[32];

    const int n0 = tid * 4;                  // 4-aligned, never crosses a g1 block
    float4 v = *reinterpret_cast<const float4*>(row + n0);

    // global max
    float m = fmaxf(fmaxf(v.x, v.y), fmaxf(v.z, v.w));
    red[tid] = m;
    __syncthreads();
    #pragma unroll
    for (int st = 128; st > 0; st >>= 1) {
        if (tid < st) red[tid] = fmaxf(red[tid], red[tid + st]);
        __syncthreads();
    }
    const float M = red[0];

    const float e0 = expf(v.x - M);
    const float e1 = expf(v.y - M);
    const float e2 = expf(v.z - M);
    const float e3 = expf(v.w - M);
    sh_e[(n0 + 0) + ((n0 + 0) >> 5)] = e0;
    sh_e[(n0 + 1) + ((n0 + 1) >> 5)] = e1;
    sh_e[(n0 + 2) + ((n0 + 2) >> 5)] = e2;
    sh_e[(n0 + 3) + ((n0 + 3) >> 5)] = e3;
    __syncthreads();

    if (tid < 32) {
        // RS[g1] = sum over g2 (contiguous 32); padded stride 33 -> conflict-free
        float s = 0.f;
        #pragma unroll
        for (int j = 0; j < 32; j++) s += sh_e[tid * 33 + j];
        RS[tid] = s;
    } else if (tid < 64) {
        // CS[g2] = sum over g1 (stride 32 -> padded 33); conflict-free
        const int g2 = tid - 32;
        float s = 0.f;
        #pragma unroll
        for (int j = 0; j < 32; j++) s += sh_e[j * 33 + g2];
        CS[g2] = s;
    }
    __syncthreads();

    const int g1 = n0 >> 5;
    const int g2 = n0 & 31;
    const float rs = RS[g1];
    const float c0 = e0 * e0 / (rs * CS[g2 + 0]);
    const float c1 = e1 * e1 / (rs * CS[g2 + 1]);
    const float c2 = e2 * e2 / (rs * CS[g2 + 2]);
    const float c3 = e3 * e3 / (rs * CS[g2 + 3]);

    red[tid] = c0 + c1 + c2 + c3;
    __syncthreads();
    #pragma unroll
    for (int st = 128; st > 0; st >>= 1) {
        if (tid < st) red[tid] += red[tid + st];
        __syncthreads();
    }
    const float inv = 1.0f / (red[0] + 1e-8f);

    v.x = c0 * inv; v.y = c1 * inv; v.z = c2 * inv; v.w = c3 * inv;
    *reinterpret_cast<float4*>(row + n0) = v;
}

// ---------------------------------------------------------------------------
extern "C" void kernel_launch(void* const* d_in, const int* in_sizes, int n_in,
                              void* d_out, int out_size) {
    const float* x = (const float*)d_in[0];        // [B, 1024]
    const float* w = (const float*)d_in[1];        // [32, 32, 1024] == [1024, 1024]
    float* out = (float*)d_out;                    // [B, 1024]

    const int D = 1024;
    const int N = 1024;
    const int Bt = in_sizes[0] / D;                // 16384

    float* logits = nullptr;
    float* wsq    = nullptr;
    cudaGetSymbolAddress((void**)&logits, g_logits);
    cudaGetSymbolAddress((void**)&wsq,    g_wsq);

    // 1) ||w||^2
    wsq_kernel<<<N, 256>>>(w, wsq);
    // 2) logits = 2*x@W^T - wsq   (x_sq cancels under both softmaxes)
    sgemm_kernel<1, true><<<dim3(N / BN, Bt / BM), 256>>>(x, w, logits, Bt, N, D, wsq);
    // 3) double softmax + product + normalize, in place
    combine_kernel<<<Bt, 256>>>(logits);
    // 4) recon = combined @ W
    sgemm_kernel<0, false><<<dim3(N / BN, Bt / BM), 256>>>(logits, w, out, Bt, N, N, nullptr);
}

// round 3
// speedup vs baseline: 1.8775x; 1.8775x over previous
#include <cuda_runtime.h>
#include <cuda_fp16.h>
#include <math.h>
#include <stdint.h>

// Problem shape (fixed): B=16384 rows, D=1024, grid 32x32 -> N=1024 codes
#define BROWS 16384
#define DIM   1024
#define NCODE 1024

// ---------------- scratch (__device__ globals; allocation-free rule) -------
__device__ float g_logits[(size_t)BROWS * NCODE];    // 64MB
__device__ float g_wsq[NCODE];
__device__ __half g_xhi[(size_t)BROWS * DIM];
__device__ __half g_xlo[(size_t)BROWS * DIM];
__device__ __half g_whi[(size_t)NCODE * DIM];
__device__ __half g_wlo[(size_t)NCODE * DIM];
__device__ __half g_wthi[(size_t)DIM * NCODE];
__device__ __half g_wtlo[(size_t)DIM * NCODE];
__device__ __half g_phi[(size_t)BROWS * NCODE];
__device__ __half g_plo[(size_t)BROWS * NCODE];

// ---------------- PTX helpers ----------------------------------------------
__device__ __forceinline__ uint32_t s2u(const void* p) {
    uint32_t a;
    asm("{ .reg .u64 t; cvta.to.shared.u64 t, %1; cvt.u32.u64 %0, t; }" : "=r"(a) : "l"(p));
    return a;
}
__device__ __forceinline__ uint32_t swz128(uint32_t o) { return o ^ ((o >> 3) & 0x70); }

__device__ __forceinline__ void cpa16(uint32_t dst, const void* src) {
    asm volatile("cp.async.cg.shared.global [%0], [%1], 16;" :: "r"(dst), "l"(src));
}
#define CP_COMMIT() asm volatile("cp.async.commit_group;")
#define CP_WAIT(n)  asm volatile("cp.async.wait_group %0;" :: "n"(n))

__device__ __forceinline__ void ldsm_x4(uint32_t* r, uint32_t addr) {
    asm volatile("ldmatrix.sync.aligned.m8n8.x4.shared.b16 {%0,%1,%2,%3}, [%4];"
                 : "=r"(r[0]), "=r"(r[1]), "=r"(r[2]), "=r"(r[3]) : "r"(addr));
}
__device__ __forceinline__ void mma16816(float* d, const uint32_t* a, const uint32_t* b) {
    asm volatile("mma.sync.aligned.m16n8k16.row.col.f32.f16.f16.f32 "
                 "{%0,%1,%2,%3}, {%4,%5,%6,%7}, {%8,%9}, {%0,%1,%2,%3};"
                 : "+f"(d[0]), "+f"(d[1]), "+f"(d[2]), "+f"(d[3])
                 : "r"(a[0]), "r"(a[1]), "r"(a[2]), "r"(a[3]), "r"(b[0]), "r"(b[1]));
}

// ---------------- small kernels ---------------------------------------------
__global__ void wsq_kernel(const float* __restrict__ W, float* __restrict__ wsq) {
    const int n = blockIdx.x, tid = threadIdx.x;
    const float4 v = *reinterpret_cast<const float4*>(W + (size_t)n * DIM + tid * 4);
    float s = v.x * v.x + v.y * v.y + v.z * v.z + v.w * v.w;
    __shared__ float red[256];
    red[tid] = s;
    __syncthreads();
    #pragma unroll
    for (int st = 128; st > 0; st >>= 1) {
        if (tid < st) red[tid] += red[tid + st];
        __syncthreads();
    }
    if (tid == 0) wsq[n] = red[0];
}

// hi = f16(v), lo = f16(v - hi). 4 elems/thread.
__global__ void split_kernel(const float* __restrict__ src,
                             __half* __restrict__ hi, __half* __restrict__ lo, int n4) {
    int i = blockIdx.x * blockDim.x + threadIdx.x;
    if (i >= n4) return;
    float4 v = reinterpret_cast<const float4*>(src)[i];
    __half h0 = __float2half_rn(v.x), h1 = __float2half_rn(v.y);
    __half h2 = __float2half_rn(v.z), h3 = __float2half_rn(v.w);
    __half l0 = __float2half_rn(v.x - __half2float(h0));
    __half l1 = __float2half_rn(v.y - __half2float(h1));
    __half l2 = __float2half_rn(v.z - __half2float(h2));
    __half l3 = __float2half_rn(v.w - __half2float(h3));
    __half2* ph = reinterpret_cast<__half2*>(hi) + 2 * i;
    __half2* pl = reinterpret_cast<__half2*>(lo) + 2 * i;
    ph[0] = __halves2half2(h0, h1); ph[1] = __halves2half2(h2, h3);
    pl[0] = __halves2half2(l0, l1); pl[1] = __halves2half2(l2, l3);
}

// W[n][d] -> WT[d][n] with f16 hi/lo split. block (32,32), grid (32,32).
__global__ void wt_split_kernel(const float* __restrict__ W,
                                __half* __restrict__ WThi, __half* __restrict__ WTlo) {
    __shared__ float tile[32][33];
    const int tx = threadIdx.x, ty = threadIdx.y;
    const int bd = blockIdx.x, bn = blockIdx.y;
    tile[ty][tx] = W[(size_t)(bn * 32 + ty) * DIM + bd * 32 + tx];
    __syncthreads();
    float v = tile[tx][ty];
    __half h = __float2half_rn(v);
    __half l = __float2half_rn(v - __half2float(h));
    const size_t o = (size_t)(bd * 32 + ty) * NCODE + bn * 32 + tx;
    WThi[o] = h;
    WTlo[o] = l;
}

// per-row double softmax + product + normalize; emits f16 hi/lo split of P
__global__ void combine_kernel(const float* __restrict__ L,
                               __half* __restrict__ Phi, __half* __restrict__ Plo) {
    const int b = blockIdx.x, tid = threadIdx.x;
    const float* row = L + (size_t)b * 1024;

    __shared__ float sh_e[1024 + 32];
    __shared__ float red[256];
    __shared__ float RS[32], CS[32];

    const int n0 = tid * 4;
    float4 v = *reinterpret_cast<const float4*>(row + n0);

    float m = fmaxf(fmaxf(v.x, v.y), fmaxf(v.z, v.w));
    red[tid] = m;
    __syncthreads();
    #pragma unroll
    for (int st = 128; st > 0; st >>= 1) {
        if (tid < st) red[tid] = fmaxf(red[tid], red[tid + st]);
        __syncthreads();
    }
    const float M = red[0];

    const float e0 = expf(v.x - M), e1 = expf(v.y - M);
    const float e2 = expf(v.z - M), e3 = expf(v.w - M);
    sh_e[(n0 + 0) + ((n0 + 0) >> 5)] = e0;
    sh_e[(n0 + 1) + ((n0 + 1) >> 5)] = e1;
    sh_e[(n0 + 2) + ((n0 + 2) >> 5)] = e2;
    sh_e[(n0 + 3) + ((n0 + 3) >> 5)] = e3;
    __syncthreads();

    if (tid < 32) {
        float s = 0.f;
        #pragma unroll
        for (int j = 0; j < 32; j++) s += sh_e[tid * 33 + j];
        RS[tid] = s;
    } else if (tid < 64) {
        const int g2 = tid - 32;
        float s = 0.f;
        #pragma unroll
        for (int j = 0; j < 32; j++) s += sh_e[j * 33 + g2];
        CS[g2] = s;
    }
    __syncthreads();

    const int g1 = n0 >> 5, g2 = n0 & 31;
    const float rs = RS[g1];
    const float c0 = e0 * e0 / (rs * CS[g2 + 0]);
    const float c1 = e1 * e1 / (rs * CS[g2 + 1]);
    const float c2 = e2 * e2 / (rs * CS[g2 + 2]);
    const float c3 = e3 * e3 / (rs * CS[g2 + 3]);

    red[tid] = c0 + c1 + c2 + c3;
    __syncthreads();
    #pragma unroll
    for (int st = 128; st > 0; st >>= 1) {
        if (tid < st) red[tid] += red[tid + st];
        __syncthreads();
    }
    const float inv = 1.0f / (red[0] + 1e-8f);

    const float o0 = c0 * inv, o1 = c1 * inv, o2 = c2 * inv, o3 = c3 * inv;
    __half h0 = __float2half_rn(o0), h1 = __float2half_rn(o1);
    __half h2 = __float2half_rn(o2), h3 = __float2half_rn(o3);
    __half l0 = __float2half_rn(o0 - __half2float(h0));
    __half l1 = __float2half_rn(o1 - __half2float(h1));
    __half l2 = __float2half_rn(o2 - __half2float(h2));
    __half l3 = __float2half_rn(o3 - __half2float(h3));
    __half2* ph = reinterpret_cast<__half2*>(Phi + (size_t)b * 1024 + n0);
    __half2* pl = reinterpret_cast<__half2*>(Plo + (size_t)b * 1024 + n0);
    ph[0] = __halves2half2(h0, h1); ph[1] = __halves2half2(h2, h3);
    pl[0] = __halves2half2(l0, l1); pl[1] = __halves2half2(l2, l3);
}

// ---------------- mma.sync split-fp16 GEMM ----------------------------------
// C[128mT+r, 128nT+c] = sum_k A[r,k]*B[c,k], A=Ahi+Alo, B=Bhi+Blo (lo*lo dropped)
// EPI=1: C = 2*acc - wsq[col].
#define TILE16   16384                 // one 128x64 f16 tile (128 rows x 128B)
#define STAGE_B  (4 * TILE16)          // Ahi, Alo, Bhi, Blo
#define STAGES   3
#define TSTAGES  16                    // 1024 / 64
#define SMEM_DYN (STAGES * STAGE_B + 1024)

template<int EPI>
__global__ __launch_bounds__(256, 1)
void mma_gemm(const __half* __restrict__ Ahi, const __half* __restrict__ Alo,
              const __half* __restrict__ Bhi, const __half* __restrict__ Blo,
              float* __restrict__ C, const float* __restrict__ wsq)
{
    extern __shared__ char dyn[];
    const uint32_t sbase = (s2u(dyn) + 1023u) & ~1023u;

    const int tid  = threadIdx.x;
    const int w    = tid >> 5, lane = tid & 31;
    const int nT   = blockIdx.x, mT = blockIdx.y;
    const int wm   = (w >> 2) * 64;    // 2 warps along m
    const int wn   = (w & 3) * 32;     // 4 warps along n

    // ---- gmem loader geometry: thread covers row tid>>1, 64B half-row ------
    const int lr = tid >> 1;
    const uint32_t lc = (tid & 1) * 64;
    uint32_t lso[4];
    #pragma unroll
    for (int i = 0; i < 4; i++) lso[i] = swz128((uint32_t)lr * 128u + lc + i * 16);

    const char* gAhi = (const char*)Ahi + (size_t)(mT * 128 + lr) * 2048 + lc;
    const char* gAlo = (const char*)Alo + (size_t)(mT * 128 + lr) * 2048 + lc;
    const char* gBhi = (const char*)Bhi + (size_t)(nT * 128 + lr) * 2048 + lc;
    const char* gBlo = (const char*)Blo + (size_t)(nT * 128 + lr) * 2048 + lc;

    auto load_stage = [&](int t, int slot) {
        const uint32_t sb = sbase + (uint32_t)slot * STAGE_B;
        const size_t tb = (size_t)t * 128;   // 64 f16 = 128B along K
        #pragma unroll
        for (int i = 0; i < 4; i++) {
            const size_t go = tb + i * 16;
            cpa16(sb + 0 * TILE16 + lso[i], gAhi + go);
            cpa16(sb + 1 * TILE16 + lso[i], gAlo + go);
            cpa16(sb + 2 * TILE16 + lso[i], gBhi + go);
            cpa16(sb + 3 * TILE16 + lso[i], gBlo + go);
        }
        CP_COMMIT();
    };

    // ---- ldmatrix base addresses (swizzled, kb folds in via XOR) -----------
    // A fragment (m16k16, x4): lanes 0-15 rows, bit4 of lane selects k-half
    uint32_t a0[4];
    {
        const int rsel = (lane >> 4) * 16;
        #pragma unroll
        for (int mi = 0; mi < 4; mi++) {
            const int row = wm + mi * 16 + (lane & 15);
            a0[mi] = (uint32_t)row * 128u + (uint32_t)(rsel ^ ((row & 7) << 4));
        }
    }
    // B fragments (two n8-tiles per x4): lanes0-7 n0..7/k0, 8-15 n0..7/k8,
    // 16-23 n8..15/k0, 24-31 n8..15/k8
    uint32_t b0[2];
    {
        const int selb = ((lane >> 3) & 1) * 16;
        #pragma unroll
        for (int p = 0; p < 2; p++) {
            const int row = wn + p * 16 + ((lane >> 4) << 3) + (lane & 7);
            b0[p] = (uint32_t)row * 128u + (uint32_t)(selb ^ ((row & 7) << 4));
        }
    }

    float d[4][4][4];
    #pragma unroll
    for (int i = 0; i < 4; i++)
        #pragma unroll
        for (int j = 0; j < 4; j++)
            #pragma unroll
            for (int k = 0; k < 4; k++) d[i][j][k] = 0.f;

    load_stage(0, 0);
    load_stage(1, 1);

    for (int t = 0; t < TSTAGES; t++) {
        if (t + 2 < TSTAGES) {
            load_stage(t + 2, (t + 2) % STAGES);
            CP_WAIT(2);
        } else if (t + 1 < TSTAGES) {
            CP_WAIT(1);
        } else {
            CP_WAIT(0);
        }
        __syncthreads();

        const uint32_t sb = sbase + (uint32_t)(t % STAGES) * STAGE_B;
        #pragma unroll
        for (int k16 = 0; k16 < 4; k16++) {
            const uint32_t kb = (uint32_t)k16 * 32;
            uint32_t ah[16], bh[8], bl[8];
            #pragma unroll
            for (int mi = 0; mi < 4; mi++) ldsm_x4(&ah[mi * 4], sb + (a0[mi] ^ kb));
            #pragma unroll
            for (int p = 0; p < 2; p++) ldsm_x4(&bh[p * 4], sb + 2 * TILE16 + (b0[p] ^ kb));
            #pragma unroll
            for (int mi = 0; mi < 4; mi++)
                #pragma unroll
                for (int nj = 0; nj < 4; nj++)
                    mma16816(d[mi][nj], &ah[mi * 4], &bh[(nj >> 1) * 4 + (nj & 1) * 2]);

            #pragma unroll
            for (int p = 0; p < 2; p++) ldsm_x4(&bl[p * 4], sb + 3 * TILE16 + (b0[p] ^ kb));
            #pragma unroll
            for (int mi = 0; mi < 4; mi++)
                #pragma unroll
                for (int nj = 0; nj < 4; nj++)
                    mma16816(d[mi][nj], &ah[mi * 4], &bl[(nj >> 1) * 4 + (nj & 1) * 2]);

            #pragma unroll
            for (int mi = 0; mi < 4; mi++) ldsm_x4(&ah[mi * 4], sb + TILE16 + (a0[mi] ^ kb));
            #pragma unroll
            for (int mi = 0; mi < 4; mi++)
                #pragma unroll
                for (int nj = 0; nj < 4; nj++)
                    mma16816(d[mi][nj], &ah[mi * 4], &bh[(nj >> 1) * 4 + (nj & 1) * 2]);
        }
        __syncthreads();
    }

    // ---- epilogue -----------------------------------------------------------
    #pragma unroll
    for (int mi = 0; mi < 4; mi++) {
        const int row0 = mT * 128 + wm + mi * 16 + (lane >> 2);
        #pragma unroll
        for (int nj = 0; nj < 4; nj++) {
            const int col = nT * 128 + wn + nj * 8 + (lane & 3) * 2;
            float w0, w1;
            if (EPI == 1) { w0 = __ldg(&wsq[col]); w1 = __ldg(&wsq[col + 1]); }
            float2 o0, o1;
            if (EPI == 1) {
                o0.x = 2.f * d[mi][nj][0] - w0; o0.y = 2.f * d[mi][nj][1] - w1;
                o1.x = 2.f * d[mi][nj][2] - w0; o1.y = 2.f * d[mi][nj][3] - w1;
            } else {
                o0.x = d[mi][nj][0]; o0.y = d[mi][nj][1];
                o1.x = d[mi][nj][2]; o1.y = d[mi][nj][3];
            }
            *reinterpret_cast<float2*>(C + (size_t)row0 * 1024 + col) = o0;
            *reinterpret_cast<float2*>(C + (size_t)(row0 + 8) * 1024 + col) = o1;
        }
    }
}

// ---------------------------------------------------------------------------
extern "C" void kernel_launch(void* const* d_in, const int* in_sizes, int n_in,
                              void* d_out, int out_size) {
    const float* x = (const float*)d_in[0];   // [16384, 1024]
    const float* w = (const float*)d_in[1];   // [32, 32, 1024] = [1024, 1024]
    float* out = (float*)d_out;               // [16384, 1024]

    float *logits, *wsq;
    __half *xhi, *xlo, *whi, *wlo, *wthi, *wtlo, *phi, *plo;
    cudaGetSymbolAddress((void**)&logits, g_logits);
    cudaGetSymbolAddress((void**)&wsq,    g_wsq);
    cudaGetSymbolAddress((void**)&xhi,    g_xhi);
    cudaGetSymbolAddress((void**)&xlo,    g_xlo);
    cudaGetSymbolAddress((void**)&whi,    g_whi);
    cudaGetSymbolAddress((void**)&wlo,    g_wlo);
    cudaGetSymbolAddress((void**)&wthi,   g_wthi);
    cudaGetSymbolAddress((void**)&wtlo,   g_wtlo);
    cudaGetSymbolAddress((void**)&phi,    g_phi);
    cudaGetSymbolAddress((void**)&plo,    g_plo);

    cudaFuncSetAttribute(mma_gemm<1>, cudaFuncAttributeMaxDynamicSharedMemorySize, SMEM_DYN);
    cudaFuncSetAttribute(mma_gemm<0>, cudaFuncAttributeMaxDynamicSharedMemorySize, SMEM_DYN);

    // prologue conversions
    wsq_kernel<<<NCODE, 256>>>(w, wsq);
    const int xn4 = BROWS * DIM / 4;
    split_kernel<<<(xn4 + 255) / 256, 256>>>(x, xhi, xlo, xn4);
    const int wn4 = NCODE * DIM / 4;
    split_kernel<<<(wn4 + 255) / 256, 256>>>(w, whi, wlo, wn4);
    wt_split_kernel<<<dim3(32, 32), dim3(32, 32)>>>(w, wthi, wtlo);

    // GEMM1: logits = 2*x@W^T - wsq   (x_sq cancels under the softmaxes)
    mma_gemm<1><<<dim3(NCODE / 128, BROWS / 128), 256, SMEM_DYN>>>(
        xhi, xlo, whi, wlo, logits, wsq);

    // combine: double softmax + product + normalize -> P (f16 hi/lo)
    combine_kernel<<<BROWS, 256>>>(logits, phi, plo);

    // GEMM2: out = P @ W   (B operand = W^T stored [d][code], K-major)
    mma_gemm<0><<<dim3(DIM / 128, BROWS / 128), 256, SMEM_DYN>>>(
        phi, plo, wthi, wtlo, out, nullptr);
}